// round 2
// baseline (speedup 1.0000x reference)
#include <cuda_runtime.h>
#include <cstdint>

// ============================================================================
// out[z,k] = sum_{i,j} M[k,i,j] * f1[z,i] * f2[z,j]
// Dense tf32 warp-MMA GEMM:  out = P @ W,
//   P[z, i*32+j] = f1[z,i]*f2[z,j]   (generated in registers, never stored)
//   W[i*32+j, k] = M[k,i,j]          (pre-packed to mma fragment order)
//
// NOTE: harness compiles to PTX target sm_103 (base, no 'a') -> tcgen05 is
// unavailable. mma.sync.m16n8k8 tf32 is base-ISA (sm_80+) and works.
//
// Tiling: CTA = 256 z rows, 512 threads = 16 warps, one m16 tile per warp,
// full n=64 per warp (8 n8 tiles), K loop = 128 chunks of k=8.
// ============================================================================

#define N_I 32
#define N_J 32
#define N_K 64
#define Z_CTA 256
#define NTHREADS 512
#define N_CHUNKS 128            // 1024 / 8

// Packed W: [chunk][lane][16 slots], slot = nt*2 + b  (nt = n-tile 0..7)
//   b0 of tile nt = W[chunk*8 + lane%4    ][nt*8 + lane/4]
//   b1 of tile nt = W[chunk*8 + lane%4 + 4][nt*8 + lane/4]
// values stored already rounded to tf32.
__device__ float g_Wp[N_CHUNKS * 32 * 16];   // 65536 floats = 256 KB

static __device__ __forceinline__ uint32_t f32_to_tf32_rn(float x) {
    uint32_t r;
    asm("cvt.rn.tf32.f32 %0, %1;" : "=r"(r) : "f"(x));
    return r;
}

// ---------------------------------------------------------------------------
// Setup kernel: pack M[k,i,j] -> g_Wp in fragment order, tf32-rounded.
// ---------------------------------------------------------------------------
__global__ void etp_pack_kernel(const float* __restrict__ Mx) {
    int idx = blockIdx.x * blockDim.x + threadIdx.x;   // 0..65535
    int chunk = idx >> 9;          // /512
    int rem   = idx & 511;
    int lane  = rem >> 4;
    int slot  = rem & 15;
    int nt    = slot >> 1;
    int b     = slot & 1;
    int n     = nt * 8 + (lane >> 2);          // output channel k
    int krow  = (lane & 3) + 4 * b;            // k-within-chunk 0..7
    int i     = chunk >> 2;
    int j     = ((chunk & 3) << 3) + krow;
    float v = Mx[n * (N_I * N_J) + i * N_J + j];
    g_Wp[idx] = __uint_as_float(f32_to_tf32_rn(v));
}

// ---------------------------------------------------------------------------

#define MMA_TF32(c, a0, a1, a2, a3, b0, b1)                                   \
    asm volatile(                                                             \
        "mma.sync.aligned.m16n8k8.row.col.f32.tf32.tf32.f32 "                 \
        "{%0,%1,%2,%3}, {%4,%5,%6,%7}, {%8,%9}, {%0,%1,%2,%3};"               \
        : "+f"((c)[0]), "+f"((c)[1]), "+f"((c)[2]), "+f"((c)[3])              \
        : "r"(a0), "r"(a1), "r"(a2), "r"(a3), "r"(b0), "r"(b1))

__global__ void __launch_bounds__(NTHREADS)
etp_mma_kernel(const float* __restrict__ F1,
               const float* __restrict__ F2,
               float* __restrict__ Out) {
    // f1 CTA tile, padded rows (36 floats) for conflict-free column reads
    __shared__ float f1s[Z_CTA * 36];

    const int tid  = threadIdx.x;
    const int warp = tid >> 5;
    const int lane = tid & 31;
    const int c    = lane & 3;          // quad column
    const int qr   = lane >> 2;         // quad row 0..7

    // ---- stage f1 tile (coalesced float4) ----
    {
        const float4* f1g = reinterpret_cast<const float4*>(
            F1 + (size_t)blockIdx.x * Z_CTA * N_I);
#pragma unroll
        for (int t = 0; t < 4; t++) {
            int i4 = tid + t * NTHREADS;         // 0..2047
            float4 v = __ldg(f1g + i4);
            int row = i4 >> 3, cg = i4 & 7;
            *reinterpret_cast<float4*>(&f1s[row * 36 + cg * 4]) = v;
        }
    }
    __syncthreads();

    // warp's m16 tile: rows [warp*16, warp*16+16)
    const int r0loc = warp * 16 + qr;            // row in CTA for c0/c1
    const size_t z0 = (size_t)blockIdx.x * Z_CTA + r0loc;
    const size_t z1 = z0 + 8;

    // ---- f2 operand values in registers: slot s = cg*2 + h -> j = 8cg+c+4h
    float f2a[8], f2b[8];
#pragma unroll
    for (int cg = 0; cg < 4; cg++) {
#pragma unroll
        for (int h = 0; h < 2; h++) {
            int j = 8 * cg + c + 4 * h;
            f2a[cg * 2 + h] = __ldg(F2 + z0 * N_J + j);
            f2b[cg * 2 + h] = __ldg(F2 + z1 * N_J + j);
        }
    }

    float C[8][4];
#pragma unroll
    for (int nt = 0; nt < 8; nt++)
#pragma unroll
        for (int q = 0; q < 4; q++) C[nt][q] = 0.0f;

    // ---- B prefetch (chunk 0) ----
    const float4* wp = reinterpret_cast<const float4*>(g_Wp);
    float4 bn0, bn1, bn2, bn3;
    {
        const float4* p = wp + lane * 4;
        bn0 = __ldg(p + 0); bn1 = __ldg(p + 1);
        bn2 = __ldg(p + 2); bn3 = __ldg(p + 3);
    }

#pragma unroll 1
    for (int ig = 0; ig < N_I; ig++) {           // i = ig
        const float f1a = f1s[r0loc * 36 + ig];
        const float f1b = f1s[(r0loc + 8) * 36 + ig];

        uint32_t pa[8], pb[8];
#pragma unroll
        for (int s = 0; s < 8; s++) {
            pa[s] = f32_to_tf32_rn(f1a * f2a[s]);
            pb[s] = f32_to_tf32_rn(f1b * f2b[s]);
        }

#pragma unroll
        for (int cc = 0; cc < 4; cc++) {
            const float4 b0 = bn0, b1 = bn1, b2 = bn2, b3 = bn3;

            const int chunk = ig * 4 + cc;
            if (chunk < N_CHUNKS - 1) {          // prefetch next chunk
                const float4* p = wp + (size_t)(chunk + 1) * 128 + lane * 4;
                bn0 = __ldg(p + 0); bn1 = __ldg(p + 1);
                bn2 = __ldg(p + 2); bn3 = __ldg(p + 3);
            }

            const uint32_t a0 = pa[cc * 2 + 0];
            const uint32_t a1 = pb[cc * 2 + 0];
            const uint32_t a2 = pa[cc * 2 + 1];
            const uint32_t a3 = pb[cc * 2 + 1];

            MMA_TF32(C[0], a0, a1, a2, a3, __float_as_uint(b0.x), __float_as_uint(b0.y));
            MMA_TF32(C[1], a0, a1, a2, a3, __float_as_uint(b0.z), __float_as_uint(b0.w));
            MMA_TF32(C[2], a0, a1, a2, a3, __float_as_uint(b1.x), __float_as_uint(b1.y));
            MMA_TF32(C[3], a0, a1, a2, a3, __float_as_uint(b1.z), __float_as_uint(b1.w));
            MMA_TF32(C[4], a0, a1, a2, a3, __float_as_uint(b2.x), __float_as_uint(b2.y));
            MMA_TF32(C[5], a0, a1, a2, a3, __float_as_uint(b2.z), __float_as_uint(b2.w));
            MMA_TF32(C[6], a0, a1, a2, a3, __float_as_uint(b3.x), __float_as_uint(b3.y));
            MMA_TF32(C[7], a0, a1, a2, a3, __float_as_uint(b3.z), __float_as_uint(b3.w));
        }
    }

    // ---- epilogue: C layout c0:(r0, 2c) c1:(r0, 2c+1) c2:(r0+8, 2c) c3:+1
    {
        float2* o0 = reinterpret_cast<float2*>(Out + z0 * N_K + 2 * c);
        float2* o1 = reinterpret_cast<float2*>(Out + z1 * N_K + 2 * c);
#pragma unroll
        for (int nt = 0; nt < 8; nt++) {
            o0[nt * 4] = make_float2(C[nt][0], C[nt][1]);   // nt*8 floats = 4 float2
            o1[nt * 4] = make_float2(C[nt][2], C[nt][3]);
        }
    }
}

// ---------------------------------------------------------------------------

extern "C" void kernel_launch(void* const* d_in, const int* in_sizes, int n_in,
                              void* d_out, int out_size) {
    const float* f1 = (const float*)d_in[0];   // [Z, 32]
    const float* f2 = (const float*)d_in[1];   // [Z, 32]
    const float* mx = (const float*)d_in[2];   // [64, 32, 32]
    float* out = (float*)d_out;                // [Z, 64]

    const int z_total = in_sizes[0] / N_I;     // 131072
    const int blocks = z_total / Z_CTA;        // 512

    etp_pack_kernel<<<256, 256>>>(mx);
    etp_mma_kernel<<<blocks, NTHREADS>>>(f1, f2, out);
}

// round 3
// speedup vs baseline: 2.4044x; 2.4044x over previous
#include <cuda_runtime.h>
#include <cstdint>

// ============================================================================
// out[z,k] = sum_{i,j} M[k,i,j] * f1[z,i] * f2[z,j]
// Dense tf32 warp-MMA GEMM:  out = P @ W
//   P[z, i*32+j] = f1[z,i]*f2[z,j]   (generated in registers)
//   W[i*32+j, k] = M[k,i,j]          (pre-packed to fragment order)
//
// R3: warp tile m32 x n32 (halves B-fragment L1 traffic per MMA vs m16n64),
//     256-thread CTAs x 2 CTAs/SM (reg cap 128) for 50% occupancy.
// ============================================================================

#define N_I 32
#define N_J 32
#define N_K 64
#define Z_CTA 128              // 4 m-groups x 32 rows
#define NTHREADS 256           // 8 warps = 4 m-groups x 2 n-halves
#define N_CHUNKS 128           // K = 1024 / 8

// Packed W layout: [chunk][nhalf][lane][slot0..7], slot = nt*2 + b
//   value = tf32( M[n, i, j] ), n = nhalf*32 + nt*8 + qr,
//   kk = c + 4b, i = chunk/4, j = (chunk%4)*8 + kk   (lane: qr=lane/4, c=lane%4)
__device__ float g_Wp[N_CHUNKS * 512];   // 256 KB

static __device__ __forceinline__ uint32_t f32_to_tf32_rn(float x) {
    uint32_t r;
    asm("cvt.rn.tf32.f32 %0, %1;" : "=r"(r) : "f"(x));
    return r;
}

// ---------------------------------------------------------------------------
__global__ void etp_pack_kernel(const float* __restrict__ Mx) {
    int idx = blockIdx.x * blockDim.x + threadIdx.x;   // 0..65535
    int chunk = idx >> 9;
    int rem   = idx & 511;
    int nhalf = rem >> 8;
    int r2    = rem & 255;
    int lane  = r2 >> 3;
    int slot  = r2 & 7;
    int nt    = slot >> 1;
    int b     = slot & 1;
    int qr    = lane >> 2;
    int c     = lane & 3;
    int n     = nhalf * 32 + nt * 8 + qr;
    int kk    = c + 4 * b;
    int i     = chunk >> 2;
    int j     = ((chunk & 3) << 3) + kk;
    float v = Mx[n * (N_I * N_J) + i * N_J + j];
    g_Wp[idx] = __uint_as_float(f32_to_tf32_rn(v));
}

// ---------------------------------------------------------------------------

#define MMA_TF32(cacc, a0, a1, a2, a3, b0, b1)                                \
    asm volatile(                                                             \
        "mma.sync.aligned.m16n8k8.row.col.f32.tf32.tf32.f32 "                 \
        "{%0,%1,%2,%3}, {%4,%5,%6,%7}, {%8,%9}, {%0,%1,%2,%3};"               \
        : "+f"((cacc)[0]), "+f"((cacc)[1]), "+f"((cacc)[2]), "+f"((cacc)[3])  \
        : "r"(a0), "r"(a1), "r"(a2), "r"(a3), "r"(b0), "r"(b1))

__global__ void __launch_bounds__(NTHREADS, 2)
etp_mma_kernel(const float* __restrict__ F1,
               const float* __restrict__ F2,
               float* __restrict__ Out) {
    // padded rows (36 floats) -> conflict-free column reads
    __shared__ float f1s[Z_CTA * 36];
    __shared__ float f2s[Z_CTA * 36];

    const int tid    = threadIdx.x;
    const int warp   = tid >> 5;
    const int lane   = tid & 31;
    const int mgroup = warp >> 1;        // 0..3, 32 rows each
    const int nhalf  = warp & 1;         // n columns [nhalf*32, +32)
    const int qr     = lane >> 2;        // 0..7
    const int c      = lane & 3;         // 0..3

    // ---- stage f1, f2 tiles (coalesced float4) ----
    {
        const float4* f1g = reinterpret_cast<const float4*>(
            F1 + (size_t)blockIdx.x * Z_CTA * N_I);
        const float4* f2g = reinterpret_cast<const float4*>(
            F2 + (size_t)blockIdx.x * Z_CTA * N_J);
#pragma unroll
        for (int t = 0; t < 4; t++) {
            int i4 = tid + t * NTHREADS;          // 0..1023
            int row = i4 >> 3, cg = i4 & 7;
            *reinterpret_cast<float4*>(&f1s[row * 36 + cg * 4]) = __ldg(f1g + i4);
            *reinterpret_cast<float4*>(&f2s[row * 36 + cg * 4]) = __ldg(f2g + i4);
        }
    }
    __syncthreads();

    // thread's 4 z rows (local): rloc[r]
    int rloc[4];
    rloc[0] = mgroup * 32 + qr;
    rloc[1] = rloc[0] + 8;
    rloc[2] = rloc[0] + 16;
    rloc[3] = rloc[0] + 24;

    // ---- f2 slots in registers: slot s=cg*2+h -> j = 8*cg + c + 4*h ----
    float f2v[4][8];
#pragma unroll
    for (int rr = 0; rr < 4; rr++) {
#pragma unroll
        for (int s = 0; s < 8; s++) {
            int cg = s >> 1, h = s & 1;
            int j = 8 * cg + c + 4 * h;
            f2v[rr][s] = f2s[rloc[rr] * 36 + j];
        }
    }

    float C[2][4][4];
#pragma unroll
    for (int mt = 0; mt < 2; mt++)
#pragma unroll
        for (int nt = 0; nt < 4; nt++)
#pragma unroll
            for (int q = 0; q < 4; q++) C[mt][nt][q] = 0.0f;

    // ---- B stream: per chunk 2x LDG.128 per lane ----
    const float4* wp = reinterpret_cast<const float4*>(g_Wp);
    const int boff = nhalf * 64 + lane * 2;      // float4 units within a chunk(128)
    float4 bA, bB;
    bA = __ldg(wp + boff);
    bB = __ldg(wp + boff + 1);

#pragma unroll 1
    for (int ig = 0; ig < N_I; ig++) {
        float f1v[4];
#pragma unroll
        for (int rr = 0; rr < 4; rr++) f1v[rr] = f1s[rloc[rr] * 36 + ig];

#pragma unroll
        for (int cc = 0; cc < 4; cc++) {
            const float4 b0 = bA, b1 = bB;

            const int chunk = ig * 4 + cc;
            if (chunk < N_CHUNKS - 1) {          // prefetch next chunk
                const float4* p = wp + (size_t)(chunk + 1) * 128 + boff;
                bA = __ldg(p);
                bB = __ldg(p + 1);
            }

            // products (A fragments), tf32-rounded
            uint32_t pr[4][2];
#pragma unroll
            for (int rr = 0; rr < 4; rr++) {
                pr[rr][0] = f32_to_tf32_rn(f1v[rr] * f2v[rr][cc * 2 + 0]);
                pr[rr][1] = f32_to_tf32_rn(f1v[rr] * f2v[rr][cc * 2 + 1]);
            }

            // mtile0: rows rloc[0], rloc[1]
            MMA_TF32(C[0][0], pr[0][0], pr[1][0], pr[0][1], pr[1][1],
                     __float_as_uint(b0.x), __float_as_uint(b0.y));
            MMA_TF32(C[0][1], pr[0][0], pr[1][0], pr[0][1], pr[1][1],
                     __float_as_uint(b0.z), __float_as_uint(b0.w));
            MMA_TF32(C[0][2], pr[0][0], pr[1][0], pr[0][1], pr[1][1],
                     __float_as_uint(b1.x), __float_as_uint(b1.y));
            MMA_TF32(C[0][3], pr[0][0], pr[1][0], pr[0][1], pr[1][1],
                     __float_as_uint(b1.z), __float_as_uint(b1.w));
            // mtile1: rows rloc[2], rloc[3]
            MMA_TF32(C[1][0], pr[2][0], pr[3][0], pr[2][1], pr[3][1],
                     __float_as_uint(b0.x), __float_as_uint(b0.y));
            MMA_TF32(C[1][1], pr[2][0], pr[3][0], pr[2][1], pr[3][1],
                     __float_as_uint(b0.z), __float_as_uint(b0.w));
            MMA_TF32(C[1][2], pr[2][0], pr[3][0], pr[2][1], pr[3][1],
                     __float_as_uint(b1.x), __float_as_uint(b1.y));
            MMA_TF32(C[1][3], pr[2][0], pr[3][0], pr[2][1], pr[3][1],
                     __float_as_uint(b1.z), __float_as_uint(b1.w));
        }
    }

    // ---- epilogue ----
    const size_t zbase = (size_t)blockIdx.x * Z_CTA;
#pragma unroll
    for (int mt = 0; mt < 2; mt++) {
        const size_t z0 = zbase + rloc[2 * mt];
        const size_t z1 = zbase + rloc[2 * mt + 1];
#pragma unroll
        for (int nt = 0; nt < 4; nt++) {
            const int col = nhalf * 32 + nt * 8 + 2 * c;
            *reinterpret_cast<float2*>(Out + z0 * N_K + col) =
                make_float2(C[mt][nt][0], C[mt][nt][1]);
            *reinterpret_cast<float2*>(Out + z1 * N_K + col) =
                make_float2(C[mt][nt][2], C[mt][nt][3]);
        }
    }
}

// ---------------------------------------------------------------------------

extern "C" void kernel_launch(void* const* d_in, const int* in_sizes, int n_in,
                              void* d_out, int out_size) {
    const float* f1 = (const float*)d_in[0];   // [Z, 32]
    const float* f2 = (const float*)d_in[1];   // [Z, 32]
    const float* mx = (const float*)d_in[2];   // [64, 32, 32]
    float* out = (float*)d_out;                // [Z, 64]

    const int z_total = in_sizes[0] / N_I;     // 131072
    const int blocks = z_total / Z_CTA;        // 1024

    etp_pack_kernel<<<256, 256>>>(mx);
    etp_mma_kernel<<<blocks, NTHREADS>>>(f1, f2, out);
}